// round 12
// baseline (speedup 1.0000x reference)
#include <cuda_runtime.h>
#include <cuda_fp16.h>

#define HID   128
#define NMAX  50000
#define EMAX  600000
#define BMAX  512
#define METAD 27

typedef unsigned int       u32;
typedef unsigned long long u64;
typedef unsigned short     u16;

// ---------------- scratch (device globals; no allocation allowed) -------------
__device__ float         g_dinv[NMAX];
__device__ unsigned char g_hsf[(size_t)NMAX * 128];  // hs messages, fp8 e4m3
__device__ __half        g_hh [(size_t)NMAX * HID];  // h activations, fp16
__device__ float         g_sum[BMAX * HID];
__device__ float         g_cnt[BMAX];
__device__ int           g_indeg[NMAX];
__device__ int           g_off  [NMAX];
__device__ int           g_cur  [NMAX];
__device__ int           g_bsum [256];
__device__ int           g_srcs [EMAX];
__device__ int           g_ei64;
__device__ int           g_ba64;

__device__ __forceinline__ int fetch_idx(const int* __restrict__ p, size_t i, int is64) {
    return is64 ? p[2 * i] : p[i];
}

__device__ __forceinline__ u32 smem_addr(const void* p) {
    u32 a;
    asm("{ .reg .u64 t; cvta.to.shared.u64 t, %1; cvt.u32.u64 %0, t; }" : "=r"(a) : "l"(p));
    return a;
}
__device__ __forceinline__ void ldsm4(u32* r, u32 addr) {
    asm volatile("ldmatrix.sync.aligned.m8n8.x4.shared.b16 {%0,%1,%2,%3}, [%4];"
        : "=r"(r[0]), "=r"(r[1]), "=r"(r[2]), "=r"(r[3]) : "r"(addr));
}
__device__ __forceinline__ void ldsm4t(u32* r, u32 addr) {
    asm volatile("ldmatrix.sync.aligned.m8n8.x4.trans.shared.b16 {%0,%1,%2,%3}, [%4];"
        : "=r"(r[0]), "=r"(r[1]), "=r"(r[2]), "=r"(r[3]) : "r"(addr));
}
__device__ __forceinline__ void mma16816(float* d, const u32* a, u32 b0, u32 b1) {
    asm volatile("mma.sync.aligned.m16n8k16.row.col.f32.f16.f16.f32 "
        "{%0,%1,%2,%3}, {%4,%5,%6,%7}, {%8,%9}, {%0,%1,%2,%3};"
        : "+f"(d[0]), "+f"(d[1]), "+f"(d[2]), "+f"(d[3])
        : "r"(a[0]), "r"(a[1]), "r"(a[2]), "r"(a[3]), "r"(b0), "r"(b1));
}
// pack: low byte <- f0, high byte <- f1  (PTX: first src -> high half)
__device__ __forceinline__ u16 pack_e4m3x2(float f0, float f1) {
    u16 r;
    asm("cvt.rn.satfinite.e4m3x2.f32 %0, %1, %2;" : "=h"(r) : "f"(f1), "f"(f0));
    return r;
}

// ---------------- init (+ dtype detect on thread 0 of block 0) ----------------
__global__ void init_kernel(const int* __restrict__ ei, const int* __restrict__ batch,
                            int E, int N, int B) {
    int i = blockIdx.x * blockDim.x + threadIdx.x;
    if (i == 0) {
        int all_zero = 1;
        for (int k = 0; k < 48; k++) {
            size_t j = (size_t)(((long long)(k + 1) * (E - 2)) / 49);
            if (ei[2 * j + 1] != 0) { all_zero = 0; break; }
        }
        g_ei64 = all_zero;
        all_zero = 1;
        for (int k = 0; k < 48; k++) {
            size_t j = (size_t)(N / 2 + ((long long)k * (N / 2 - 2)) / 48);
            if (batch[2 * (j / 2) + 1] != 0) { all_zero = 0; break; }
        }
        g_ba64 = all_zero;
    }
    if (i < N) { g_indeg[i] = 0; g_cur[i] = 0; }
    if (i < B * HID) g_sum[i] = 0.0f;
    if (i < B) g_cnt[i] = 0.0f;
}

// ---------------- in-degree histogram ------------------------------------------
__global__ void hist_kernel(const int* __restrict__ ei, int E) {
    int e = blockIdx.x * blockDim.x + threadIdx.x;
    if (e < E) atomicAdd(&g_indeg[fetch_idx(ei, (size_t)E + e, g_ei64)], 1);
}

// ---------------- scan phase 1: per-block exclusive scan ----------------------
__global__ void scan_block_kernel(int N) {
    __shared__ int sh[256];
    int i = blockIdx.x * 256 + threadIdx.x;
    int v = (i < N) ? g_indeg[i] : 0;
    sh[threadIdx.x] = v;
    __syncthreads();
#pragma unroll
    for (int s = 1; s < 256; s <<= 1) {
        int t = (threadIdx.x >= s) ? sh[threadIdx.x - s] : 0;
        __syncthreads();
        sh[threadIdx.x] += t;
        __syncthreads();
    }
    if (i < N) g_off[i] = sh[threadIdx.x] - v;
    if (threadIdx.x == 255) g_bsum[blockIdx.x] = sh[255];
}

// ---------------- scan phase 2: add block-prefix + dinv ------------------------
__global__ void scan_add_kernel(int N) {
    __shared__ int base_sh;
    if (threadIdx.x < 32) {
        int run = 0;
        for (int b = threadIdx.x; b < blockIdx.x; b += 32) run += g_bsum[b];
#pragma unroll
        for (int s = 16; s > 0; s >>= 1) run += __shfl_down_sync(0xffffffffu, run, s);
        if (threadIdx.x == 0) base_sh = run;
    }
    __syncthreads();
    int i = blockIdx.x * 256 + threadIdx.x;
    if (i < N) {
        g_off[i] += base_sh;
        g_dinv[i] = rsqrtf((float)(g_indeg[i] + 1));
    }
}

// ---------------- fill: srcs sorted by dst --------------------------------------
__global__ void fill_kernel(const int* __restrict__ ei, int E) {
    int e = blockIdx.x * blockDim.x + threadIdx.x;
    if (e >= E) return;
    int is64 = g_ei64;
    int s = fetch_idx(ei, (size_t)e, is64);
    int d = fetch_idx(ei, (size_t)E + e, is64);
    int pos = g_off[d] + atomicAdd(&g_cur[d], 1);
    g_srcs[pos] = s;
}

// ---------------- GEMM (mma.sync HMMA): hs(fp8) = dinv[row] * (A @ W) ----------
// 128x128 block tile, 8 warps (4x2), warp tile 32x64, fp32 accumulators.
#define PITCH 136
__global__ __launch_bounds__(256, 2)
void gemm_kernel(const float* __restrict__ Aext, const float* __restrict__ W,
                 int M, int use_gh)
{
    extern __shared__ __align__(16) __half smem[];
    __half* As = smem;                 // [128][PITCH]
    __half* Bs = smem + 128 * PITCH;   // [128][PITCH]

    int tid = threadIdx.x;
    int row0 = blockIdx.x * 128;
    bool full = (row0 + 128 <= M);

    // ---- fill A ----
    if (use_gh) {
#pragma unroll
        for (int i = 0; i < 8; i++) {
            int idx = i * 256 + tid;        // 2048 uint4 slots: 128 rows x 16
            int m   = idx >> 4;
            int k8  = idx & 15;
            uint4 v;
            if (full || (row0 + m) < M)
                v = *(const uint4*)(g_hh + (size_t)(row0 + m) * HID + k8 * 8);
            else
                v = make_uint4(0, 0, 0, 0);
            *(uint4*)(As + m * PITCH + k8 * 8) = v;
        }
    } else {
#pragma unroll
        for (int i = 0; i < 16; i++) {
            int idx = i * 256 + tid;        // 4096 float4 slots: 128 rows x 32
            int m   = idx >> 5;
            int k4  = idx & 31;
            float4 v;
            if (full || (row0 + m) < M)
                v = *(const float4*)(Aext + (size_t)(row0 + m) * HID + k4 * 4);
            else
                v = make_float4(0.f, 0.f, 0.f, 0.f);
            __half2 h0 = __floats2half2_rn(v.x, v.y);
            __half2 h1 = __floats2half2_rn(v.z, v.w);
            uint2 st; st.x = *(u32*)&h0; st.y = *(u32*)&h1;
            *(uint2*)(As + m * PITCH + k4 * 4) = st;
        }
    }
    // ---- fill B: W [k][n] fp32 -> fp16 ----
#pragma unroll
    for (int i = 0; i < 16; i++) {
        int idx = i * 256 + tid;
        int k   = idx >> 5;
        int n4  = idx & 31;
        float4 v = *(const float4*)(W + (size_t)k * 128 + n4 * 4);
        __half2 h0 = __floats2half2_rn(v.x, v.y);
        __half2 h1 = __floats2half2_rn(v.z, v.w);
        uint2 st; st.x = *(u32*)&h0; st.y = *(u32*)&h1;
        *(uint2*)(Bs + k * PITCH + n4 * 4) = st;
    }
    __syncthreads();

    int wid  = tid >> 5;
    int lane = tid & 31;
    int wm = (wid & 3) * 32;     // warp m offset
    int wn = (wid >> 2) * 64;    // warp n offset

    float acc[2][8][4];
#pragma unroll
    for (int mt = 0; mt < 2; mt++)
#pragma unroll
        for (int nt = 0; nt < 8; nt++)
#pragma unroll
            for (int j = 0; j < 4; j++) acc[mt][nt][j] = 0.f;

    int a_row_in = lane & 15;
    int a_koff   = (lane >> 4) * 8;
    int b_row_in = (lane & 7) + ((lane >> 3) & 1) * 8;
    int b_noff   = (lane >> 4) * 8;

#pragma unroll
    for (int ks = 0; ks < 8; ks++) {
        int k = ks * 16;
        u32 af[2][4], bf[4][4];
#pragma unroll
        for (int mt = 0; mt < 2; mt++) {
            const __half* p = As + (wm + mt * 16 + a_row_in) * PITCH + k + a_koff;
            ldsm4(af[mt], smem_addr(p));
        }
#pragma unroll
        for (int nt2 = 0; nt2 < 4; nt2++) {
            const __half* p = Bs + (k + b_row_in) * PITCH + wn + nt2 * 16 + b_noff;
            ldsm4t(bf[nt2], smem_addr(p));
        }
#pragma unroll
        for (int mt = 0; mt < 2; mt++)
#pragma unroll
            for (int nt = 0; nt < 8; nt++) {
                int g = nt >> 1, h = nt & 1;
                mma16816(acc[mt][nt], af[mt], bf[g][h * 2], bf[g][h * 2 + 1]);
            }
    }

    // ---- epilogue: scale dinv, write fp8 messages ----
    int gr = lane >> 2;
    int tc = lane & 3;
#pragma unroll
    for (int mt = 0; mt < 2; mt++) {
        int ra = row0 + wm + mt * 16 + gr;
        int rb = ra + 8;
        float dva = (ra < M) ? g_dinv[ra] : 0.f;
        float dvb = (rb < M) ? g_dinv[rb] : 0.f;
#pragma unroll
        for (int nt = 0; nt < 8; nt++) {
            int col = wn + nt * 8 + tc * 2;
            if (ra < M)
                *(u16*)(g_hsf + (size_t)ra * 128 + col) =
                    pack_e4m3x2(acc[mt][nt][0] * dva, acc[mt][nt][1] * dva);
            if (rb < M)
                *(u16*)(g_hsf + (size_t)rb * 128 + col) =
                    pack_e4m3x2(acc[mt][nt][2] * dvb, acc[mt][nt][3] * dvb);
        }
    }
}

// ---------------- gather: h[r](fp16) = relu(dinv[r]*(hs[r] + sum hs[src]) + b) -
// one warp per row; hs is fp8 e4m3 (1 LDG.32 per lane per row), fp32 accum.
__global__ void gather_kernel(const float* __restrict__ bias, int N,
                              const int* __restrict__ batch, int do_pool)
{
    int gid = blockIdx.x * blockDim.x + threadIdx.x;
    int row = gid >> 5;
    if (row >= N) return;
    int lane = gid & 31;

    const u32* hs4 = (const u32*)g_hsf;    // 4 fp8 per u32; 32 per row
    int beg = g_off[row];
    int cnt = g_indeg[row];

    float4 a  = make_float4(0.f, 0.f, 0.f, 0.f);
    float4 a1 = make_float4(0.f, 0.f, 0.f, 0.f);
#define ACC(dst, rw) do {                                               \
        u32 _v = hs4[(size_t)(rw) * 32 + lane];                          \
        u16 _s0 = (u16)_v, _s1 = (u16)(_v >> 16);                        \
        u32 _h01, _h23;                                                  \
        asm("cvt.rn.f16x2.e4m3x2 %0, %1;" : "=r"(_h01) : "h"(_s0));      \
        asm("cvt.rn.f16x2.e4m3x2 %0, %1;" : "=r"(_h23) : "h"(_s1));      \
        float2 _f0 = __half22float2(*(const __half2*)&_h01);             \
        float2 _f1 = __half22float2(*(const __half2*)&_h23);             \
        dst.x += _f0.x; dst.y += _f0.y; dst.z += _f1.x; dst.w += _f1.y;  \
    } while (0)

    ACC(a, row);
    int k = 0;
    for (; k + 4 <= cnt; k += 4) {
        int s0 = g_srcs[beg + k];
        int s1 = g_srcs[beg + k + 1];
        int s2 = g_srcs[beg + k + 2];
        int s3 = g_srcs[beg + k + 3];
        ACC(a, s0); ACC(a1, s1); ACC(a, s2); ACC(a1, s3);
    }
    for (; k < cnt; k++) ACC(a, g_srcs[beg + k]);
    a.x += a1.x; a.y += a1.y; a.z += a1.z; a.w += a1.w;
#undef ACC

    float dv = g_dinv[row];
    float4 bb = ((const float4*)bias)[lane];
    a.x = fmaxf(fmaf(a.x, dv, bb.x), 0.f);
    a.y = fmaxf(fmaf(a.y, dv, bb.y), 0.f);
    a.z = fmaxf(fmaf(a.z, dv, bb.z), 0.f);
    a.w = fmaxf(fmaf(a.w, dv, bb.w), 0.f);

    if (!do_pool) {
        __half2 h0 = __floats2half2_rn(a.x, a.y);
        __half2 h1 = __floats2half2_rn(a.z, a.w);
        uint2 st; st.x = *(u32*)&h0; st.y = *(u32*)&h1;
        *(uint2*)(g_hh + (size_t)row * HID + lane * 4) = st;
    } else {
        int b = fetch_idx(batch, (size_t)row, g_ba64);
        float* p = g_sum + b * 128 + lane * 4;
        atomicAdd(p + 0, a.x);
        atomicAdd(p + 1, a.y);
        atomicAdd(p + 2, a.z);
        atomicAdd(p + 3, a.w);
        if (lane == 0) atomicAdd(&g_cnt[b], 1.0f);
    }
}

// ---------------- MLP head ------------------------------------------------------
__global__ __launch_bounds__(128)
void head_kernel(const float* __restrict__ meta,
                 const float* __restrict__ Wh1, const float* __restrict__ bh1,
                 const float* __restrict__ Wh2, const float* __restrict__ bh2,
                 float* __restrict__ out)
{
    int b = blockIdx.x;
    int j = threadIdx.x;
    __shared__ float zin[HID + METAD];
    __shared__ float red[128];

    float inv = 1.0f / fmaxf(g_cnt[b], 1.0f);
    zin[j] = g_sum[b * HID + j] * inv;
    if (j < METAD) zin[HID + j] = meta[b * METAD + j];
    __syncthreads();

    float acc = bh1[j];
#pragma unroll
    for (int k = 0; k < HID + METAD; k++)
        acc = fmaf(zin[k], Wh1[k * HID + j], acc);
    red[j] = fmaxf(acc, 0.0f) * Wh2[j];
    __syncthreads();
#pragma unroll
    for (int s = 64; s > 0; s >>= 1) {
        if (j < s) red[j] += red[j + s];
        __syncthreads();
    }
    if (j == 0) out[b] = red[0] + bh2[0];
}

// --------------------------------------------------------------------------------
extern "C" void kernel_launch(void* const* d_in, const int* in_sizes, int n_in,
                              void* d_out, int out_size)
{
    const float* x     = (const float*)d_in[0];
    const int*   ei    = (const int*)d_in[1];
    const int*   batch = (const int*)d_in[2];
    const float* meta  = (const float*)d_in[3];
    const float* W1 = (const float*)d_in[4];  const float* b1 = (const float*)d_in[5];
    const float* W2 = (const float*)d_in[6];  const float* b2 = (const float*)d_in[7];
    const float* W3 = (const float*)d_in[8];  const float* b3 = (const float*)d_in[9];
    const float* Wh1 = (const float*)d_in[10]; const float* bh1 = (const float*)d_in[11];
    const float* Wh2 = (const float*)d_in[12]; const float* bh2 = (const float*)d_in[13];
    float* out = (float*)d_out;

    int N = in_sizes[0] / HID;
    int E = in_sizes[1] / 2;
    int B = in_sizes[3] / METAD;

    const int DSM = 2 * 128 * PITCH * (int)sizeof(__half);   // 69632
    cudaFuncSetAttribute(gemm_kernel, cudaFuncAttributeMaxDynamicSharedMemorySize, DSM);

    int initN = (N > B * HID) ? N : B * HID;
    init_kernel<<<(initN + 255) / 256, 256>>>(ei, batch, E, N, B);
    hist_kernel<<<(E + 255) / 256, 256>>>(ei, E);

    int nscan = (N + 255) / 256;
    scan_block_kernel<<<nscan, 256>>>(N);
    scan_add_kernel  <<<nscan, 256>>>(N);
    fill_kernel      <<<(E + 255) / 256, 256>>>(ei, E);

    int gblocks = (N + 127) / 128;
    int wblocks = (int)(((long long)N * 32 + 255) / 256);

    gemm_kernel  <<<gblocks, 256, DSM>>>(x, W1, N, 0);
    gather_kernel<<<wblocks, 256>>>(b1, N, batch, 0);
    gemm_kernel  <<<gblocks, 256, DSM>>>(nullptr, W2, N, 1);
    gather_kernel<<<wblocks, 256>>>(b2, N, batch, 0);
    gemm_kernel  <<<gblocks, 256, DSM>>>(nullptr, W3, N, 1);
    gather_kernel<<<wblocks, 256>>>(b3, N, batch, 1);

    head_kernel<<<B, 128>>>(meta, Wh1, bh1, Wh2, bh2, out);
}

// round 13
// speedup vs baseline: 1.0336x; 1.0336x over previous
#include <cuda_runtime.h>
#include <cuda_fp16.h>

#define HID   128
#define NMAX  50000
#define EMAX  600000
#define BMAX  512
#define METAD 27

typedef unsigned int       u32;
typedef unsigned long long u64;

// ---------------- scratch (device globals; no allocation allowed) -------------
__device__ float   g_dinv[NMAX];
__device__ __half2 g_hsh[(size_t)NMAX * 64];   // hs messages, fp16
__device__ __half  g_hh [(size_t)NMAX * HID];  // h activations, fp16
__device__ float   g_sum[BMAX * HID];
__device__ float   g_cnt[BMAX];
__device__ int     g_indeg[NMAX];
__device__ int     g_off  [NMAX];
__device__ int     g_cur  [NMAX];
__device__ int     g_bsum [256];
__device__ int     g_srcs [EMAX];
__device__ int     g_ei64;
__device__ int     g_ba64;

__device__ __forceinline__ int fetch_idx(const int* __restrict__ p, size_t i, int is64) {
    return is64 ? p[2 * i] : p[i];
}

__device__ __forceinline__ u32 smem_addr(const void* p) {
    u32 a;
    asm("{ .reg .u64 t; cvta.to.shared.u64 t, %1; cvt.u32.u64 %0, t; }" : "=r"(a) : "l"(p));
    return a;
}
__device__ __forceinline__ void ldsm4(u32* r, u32 addr) {
    asm volatile("ldmatrix.sync.aligned.m8n8.x4.shared.b16 {%0,%1,%2,%3}, [%4];"
        : "=r"(r[0]), "=r"(r[1]), "=r"(r[2]), "=r"(r[3]) : "r"(addr));
}
__device__ __forceinline__ void ldsm4t(u32* r, u32 addr) {
    asm volatile("ldmatrix.sync.aligned.m8n8.x4.trans.shared.b16 {%0,%1,%2,%3}, [%4];"
        : "=r"(r[0]), "=r"(r[1]), "=r"(r[2]), "=r"(r[3]) : "r"(addr));
}
__device__ __forceinline__ void mma16816(float* d, const u32* a, u32 b0, u32 b1) {
    asm volatile("mma.sync.aligned.m16n8k16.row.col.f32.f16.f16.f32 "
        "{%0,%1,%2,%3}, {%4,%5,%6,%7}, {%8,%9}, {%0,%1,%2,%3};"
        : "+f"(d[0]), "+f"(d[1]), "+f"(d[2]), "+f"(d[3])
        : "r"(a[0]), "r"(a[1]), "r"(a[2]), "r"(a[3]), "r"(b0), "r"(b1));
}

// ---------------- init (+ dtype detect on thread 0 of block 0) ----------------
__global__ void init_kernel(const int* __restrict__ ei, const int* __restrict__ batch,
                            int E, int N, int B) {
    int i = blockIdx.x * blockDim.x + threadIdx.x;
    if (i == 0) {
        int all_zero = 1;
        for (int k = 0; k < 48; k++) {
            size_t j = (size_t)(((long long)(k + 1) * (E - 2)) / 49);
            if (ei[2 * j + 1] != 0) { all_zero = 0; break; }
        }
        g_ei64 = all_zero;
        all_zero = 1;
        for (int k = 0; k < 48; k++) {
            size_t j = (size_t)(N / 2 + ((long long)k * (N / 2 - 2)) / 48);
            if (batch[2 * (j / 2) + 1] != 0) { all_zero = 0; break; }
        }
        g_ba64 = all_zero;
    }
    if (i < N) { g_indeg[i] = 0; g_cur[i] = 0; }
    if (i < B * HID) g_sum[i] = 0.0f;
    if (i < B) g_cnt[i] = 0.0f;
}

// ---------------- in-degree histogram ------------------------------------------
__global__ void hist_kernel(const int* __restrict__ ei, int E) {
    int e = blockIdx.x * blockDim.x + threadIdx.x;
    if (e < E) atomicAdd(&g_indeg[fetch_idx(ei, (size_t)E + e, g_ei64)], 1);
}

// ---------------- dinv = rsqrt(deg incl self loop) -----------------------------
__global__ void dinv_kernel(int N) {
    int i = blockIdx.x * blockDim.x + threadIdx.x;
    if (i < N) g_dinv[i] = rsqrtf((float)(g_indeg[i] + 1));
}

// ---------------- scan phase 1: per-block exclusive scan ----------------------
__global__ void scan_block_kernel(int N) {
    __shared__ int sh[256];
    int i = blockIdx.x * 256 + threadIdx.x;
    int v = (i < N) ? g_indeg[i] : 0;
    sh[threadIdx.x] = v;
    __syncthreads();
#pragma unroll
    for (int s = 1; s < 256; s <<= 1) {
        int t = (threadIdx.x >= s) ? sh[threadIdx.x - s] : 0;
        __syncthreads();
        sh[threadIdx.x] += t;
        __syncthreads();
    }
    if (i < N) g_off[i] = sh[threadIdx.x] - v;
    if (threadIdx.x == 255) g_bsum[blockIdx.x] = sh[255];
}

// ---------------- scan phase 2: add block prefix --------------------------------
__global__ void scan_add_kernel(int N) {
    __shared__ int base_sh;
    if (threadIdx.x < 32) {
        int run = 0;
        for (int b = threadIdx.x; b < blockIdx.x; b += 32) run += g_bsum[b];
#pragma unroll
        for (int s = 16; s > 0; s >>= 1) run += __shfl_down_sync(0xffffffffu, run, s);
        if (threadIdx.x == 0) base_sh = run;
    }
    __syncthreads();
    int i = blockIdx.x * 256 + threadIdx.x;
    if (i < N) g_off[i] += base_sh;
}

// ---------------- fill: srcs sorted by dst --------------------------------------
__global__ void fill_kernel(const int* __restrict__ ei, int E) {
    int e = blockIdx.x * blockDim.x + threadIdx.x;
    if (e >= E) return;
    int is64 = g_ei64;
    int s = fetch_idx(ei, (size_t)e, is64);
    int d = fetch_idx(ei, (size_t)E + e, is64);
    int pos = g_off[d] + atomicAdd(&g_cur[d], 1);
    g_srcs[pos] = s;
}

// ---------------- GEMM (mma.sync HMMA): hs(fp16) = dinv[row] * (A @ W) ---------
// 128x128 block tile, 8 warps (4x2), warp tile 32x64, fp32 accumulators.
#define PITCH 136
__global__ __launch_bounds__(256, 2)
void gemm_kernel(const float* __restrict__ Aext, const float* __restrict__ W,
                 int M, int use_gh)
{
    extern __shared__ __align__(16) __half smem[];
    __half* As = smem;                 // [128][PITCH]
    __half* Bs = smem + 128 * PITCH;   // [128][PITCH]

    int tid = threadIdx.x;
    int row0 = blockIdx.x * 128;
    bool full = (row0 + 128 <= M);

    // ---- fill A ----
    if (use_gh) {
#pragma unroll
        for (int i = 0; i < 8; i++) {
            int idx = i * 256 + tid;        // 2048 uint4 slots: 128 rows x 16
            int m   = idx >> 4;
            int k8  = idx & 15;
            uint4 v;
            if (full || (row0 + m) < M)
                v = *(const uint4*)(g_hh + (size_t)(row0 + m) * HID + k8 * 8);
            else
                v = make_uint4(0, 0, 0, 0);
            *(uint4*)(As + m * PITCH + k8 * 8) = v;
        }
    } else {
#pragma unroll
        for (int i = 0; i < 16; i++) {
            int idx = i * 256 + tid;        // 4096 float4 slots: 128 rows x 32
            int m   = idx >> 5;
            int k4  = idx & 31;
            float4 v;
            if (full || (row0 + m) < M)
                v = *(const float4*)(Aext + (size_t)(row0 + m) * HID + k4 * 4);
            else
                v = make_float4(0.f, 0.f, 0.f, 0.f);
            __half2 h0 = __floats2half2_rn(v.x, v.y);
            __half2 h1 = __floats2half2_rn(v.z, v.w);
            uint2 st; st.x = *(u32*)&h0; st.y = *(u32*)&h1;
            *(uint2*)(As + m * PITCH + k4 * 4) = st;
        }
    }
    // ---- fill B: W [k][n] fp32 -> fp16 ----
#pragma unroll
    for (int i = 0; i < 16; i++) {
        int idx = i * 256 + tid;
        int k   = idx >> 5;
        int n4  = idx & 31;
        float4 v = *(const float4*)(W + (size_t)k * 128 + n4 * 4);
        __half2 h0 = __floats2half2_rn(v.x, v.y);
        __half2 h1 = __floats2half2_rn(v.z, v.w);
        uint2 st; st.x = *(u32*)&h0; st.y = *(u32*)&h1;
        *(uint2*)(Bs + k * PITCH + n4 * 4) = st;
    }
    __syncthreads();

    int wid  = tid >> 5;
    int lane = tid & 31;
    int wm = (wid & 3) * 32;
    int wn = (wid >> 2) * 64;

    float acc[2][8][4];
#pragma unroll
    for (int mt = 0; mt < 2; mt++)
#pragma unroll
        for (int nt = 0; nt < 8; nt++)
#pragma unroll
            for (int j = 0; j < 4; j++) acc[mt][nt][j] = 0.f;

    int a_row_in = lane & 15;
    int a_koff   = (lane >> 4) * 8;
    int b_row_in = (lane & 7) + ((lane >> 3) & 1) * 8;
    int b_noff   = (lane >> 4) * 8;

#pragma unroll
    for (int ks = 0; ks < 8; ks++) {
        int k = ks * 16;
        u32 af[2][4], bf[4][4];
#pragma unroll
        for (int mt = 0; mt < 2; mt++) {
            const __half* p = As + (wm + mt * 16 + a_row_in) * PITCH + k + a_koff;
            ldsm4(af[mt], smem_addr(p));
        }
#pragma unroll
        for (int nt2 = 0; nt2 < 4; nt2++) {
            const __half* p = Bs + (k + b_row_in) * PITCH + wn + nt2 * 16 + b_noff;
            ldsm4t(bf[nt2], smem_addr(p));
        }
#pragma unroll
        for (int mt = 0; mt < 2; mt++)
#pragma unroll
            for (int nt = 0; nt < 8; nt++) {
                int g = nt >> 1, h = nt & 1;
                mma16816(acc[mt][nt], af[mt], bf[g][h * 2], bf[g][h * 2 + 1]);
            }
    }

    // ---- epilogue: scale dinv, write fp16 messages ----
    int gr = lane >> 2;
    int tc = lane & 3;
#pragma unroll
    for (int mt = 0; mt < 2; mt++) {
        int ra = row0 + wm + mt * 16 + gr;
        int rb = ra + 8;
        float dva = (ra < M) ? g_dinv[ra] : 0.f;
        float dvb = (rb < M) ? g_dinv[rb] : 0.f;
#pragma unroll
        for (int nt = 0; nt < 8; nt++) {
            int col = wn + nt * 8 + tc * 2;
            if (ra < M)
                g_hsh[(size_t)ra * 64 + (col >> 1)] =
                    __floats2half2_rn(acc[mt][nt][0] * dva, acc[mt][nt][1] * dva);
            if (rb < M)
                g_hsh[(size_t)rb * 64 + (col >> 1)] =
                    __floats2half2_rn(acc[mt][nt][2] * dvb, acc[mt][nt][3] * dvb);
        }
    }
}

// ---------------- gather: fp16 HADD2 accumulation, index-prefetch pipeline -----
__global__ void gather_kernel(const float* __restrict__ bias, int N,
                              const int* __restrict__ batch, int do_pool)
{
    int gid = blockIdx.x * blockDim.x + threadIdx.x;
    int row = gid >> 5;
    if (row >= N) return;
    int lane = gid & 31;

    const uint2* hs2 = (const uint2*)g_hsh;   // 4 halves per uint2; 32 per row
    const int* __restrict__ srcs = g_srcs;
    int beg = g_off[row];
    int cnt = g_indeg[row];

    // dual fp16 accumulator sets (A: even slots, B: odd slots)
    uint2 sv = hs2[(size_t)row * 32 + lane];  // self-loop term -> set A
    __half2 aAlo = *(const __half2*)&sv.x;
    __half2 aAhi = *(const __half2*)&sv.y;
    __half2 aBlo = __floats2half2_rn(0.f, 0.f);
    __half2 aBhi = aBlo;

#define ACCA(rw) do { uint2 _v = hs2[(size_t)(rw) * 32 + lane];             \
        aAlo = __hadd2(aAlo, *(const __half2*)&_v.x);                        \
        aAhi = __hadd2(aAhi, *(const __half2*)&_v.y); } while (0)
#define ACCB(rw) do { uint2 _v = hs2[(size_t)(rw) * 32 + lane];             \
        aBlo = __hadd2(aBlo, *(const __half2*)&_v.x);                        \
        aBhi = __hadd2(aBhi, *(const __half2*)&_v.y); } while (0)

    int k = 0;
    if (cnt >= 4) {
        int s0 = srcs[beg], s1 = srcs[beg + 1], s2 = srcs[beg + 2], s3 = srcs[beg + 3];
        for (; k + 8 <= cnt; k += 4) {
            int t0 = srcs[beg + k + 4], t1 = srcs[beg + k + 5];
            int t2 = srcs[beg + k + 6], t3 = srcs[beg + k + 7];
            ACCA(s0); ACCB(s1); ACCA(s2); ACCB(s3);
            s0 = t0; s1 = t1; s2 = t2; s3 = t3;
        }
        ACCA(s0); ACCB(s1); ACCA(s2); ACCB(s3);
        k += 4;
    }
    for (; k < cnt; k++) ACCA(srcs[beg + k]);
#undef ACCA
#undef ACCB

    // merge in fp32
    float2 fAlo = __half22float2(aAlo), fAhi = __half22float2(aAhi);
    float2 fBlo = __half22float2(aBlo), fBhi = __half22float2(aBhi);
    float4 a;
    a.x = fAlo.x + fBlo.x; a.y = fAlo.y + fBlo.y;
    a.z = fAhi.x + fBhi.x; a.w = fAhi.y + fBhi.y;

    float dv = g_dinv[row];
    float4 bb = ((const float4*)bias)[lane];
    a.x = fmaxf(fmaf(a.x, dv, bb.x), 0.f);
    a.y = fmaxf(fmaf(a.y, dv, bb.y), 0.f);
    a.z = fmaxf(fmaf(a.z, dv, bb.z), 0.f);
    a.w = fmaxf(fmaf(a.w, dv, bb.w), 0.f);

    if (!do_pool) {
        __half2 h0 = __floats2half2_rn(a.x, a.y);
        __half2 h1 = __floats2half2_rn(a.z, a.w);
        uint2 st; st.x = *(u32*)&h0; st.y = *(u32*)&h1;
        *(uint2*)(g_hh + (size_t)row * HID + lane * 4) = st;
    } else {
        int b = fetch_idx(batch, (size_t)row, g_ba64);
        float* p = g_sum + b * 128 + lane * 4;
        atomicAdd(p + 0, a.x);
        atomicAdd(p + 1, a.y);
        atomicAdd(p + 2, a.z);
        atomicAdd(p + 3, a.w);
        if (lane == 0) atomicAdd(&g_cnt[b], 1.0f);
    }
}

// ---------------- MLP head ------------------------------------------------------
__global__ __launch_bounds__(128)
void head_kernel(const float* __restrict__ meta,
                 const float* __restrict__ Wh1, const float* __restrict__ bh1,
                 const float* __restrict__ Wh2, const float* __restrict__ bh2,
                 float* __restrict__ out)
{
    int b = blockIdx.x;
    int j = threadIdx.x;
    __shared__ float zin[HID + METAD];
    __shared__ float red[128];

    float inv = 1.0f / fmaxf(g_cnt[b], 1.0f);
    zin[j] = g_sum[b * HID + j] * inv;
    if (j < METAD) zin[HID + j] = meta[b * METAD + j];
    __syncthreads();

    float acc = bh1[j];
#pragma unroll
    for (int k = 0; k < HID + METAD; k++)
        acc = fmaf(zin[k], Wh1[k * HID + j], acc);
    red[j] = fmaxf(acc, 0.0f) * Wh2[j];
    __syncthreads();
#pragma unroll
    for (int s = 64; s > 0; s >>= 1) {
        if (j < s) red[j] += red[j + s];
        __syncthreads();
    }
    if (j == 0) out[b] = red[0] + bh2[0];
}

// --------------------------------------------------------------------------------
extern "C" void kernel_launch(void* const* d_in, const int* in_sizes, int n_in,
                              void* d_out, int out_size)
{
    const float* x     = (const float*)d_in[0];
    const int*   ei    = (const int*)d_in[1];
    const int*   batch = (const int*)d_in[2];
    const float* meta  = (const float*)d_in[3];
    const float* W1 = (const float*)d_in[4];  const float* b1 = (const float*)d_in[5];
    const float* W2 = (const float*)d_in[6];  const float* b2 = (const float*)d_in[7];
    const float* W3 = (const float*)d_in[8];  const float* b3 = (const float*)d_in[9];
    const float* Wh1 = (const float*)d_in[10]; const float* bh1 = (const float*)d_in[11];
    const float* Wh2 = (const float*)d_in[12]; const float* bh2 = (const float*)d_in[13];
    float* out = (float*)d_out;

    int N = in_sizes[0] / HID;
    int E = in_sizes[1] / 2;
    int B = in_sizes[3] / METAD;

    const int DSM = 2 * 128 * PITCH * (int)sizeof(__half);   // 69632
    cudaFuncSetAttribute(gemm_kernel, cudaFuncAttributeMaxDynamicSharedMemorySize, DSM);

    int initN = (N > B * HID) ? N : B * HID;
    int gblocks = (N + 127) / 128;
    int wblocks = (int)(((long long)N * 32 + 255) / 256);
    int nscan   = (N + 255) / 256;

    // order puts gemm at launch slot 4 (the one ncu samples)
    init_kernel<<<(initN + 255) / 256, 256>>>(ei, batch, E, N, B);
    hist_kernel<<<(E + 255) / 256, 256>>>(ei, E);
    dinv_kernel<<<(N + 255) / 256, 256>>>(N);
    gemm_kernel<<<gblocks, 256, DSM>>>(x, W1, N, 0);            // layer-1 GEMM (slot 4)

    scan_block_kernel<<<nscan, 256>>>(N);
    scan_add_kernel  <<<nscan, 256>>>(N);
    fill_kernel      <<<(E + 255) / 256, 256>>>(ei, E);

    gather_kernel<<<wblocks, 256>>>(b1, N, batch, 0);
    gemm_kernel  <<<gblocks, 256, DSM>>>(nullptr, W2, N, 1);
    gather_kernel<<<wblocks, 256>>>(b2, N, batch, 0);
    gemm_kernel  <<<gblocks, 256, DSM>>>(nullptr, W3, N, 1);
    gather_kernel<<<wblocks, 256>>>(b3, N, batch, 1);

    head_kernel<<<B, 128>>>(meta, Wh1, bh1, Wh2, bh2, out);
}

// round 14
// speedup vs baseline: 1.0435x; 1.0095x over previous
#include <cuda_runtime.h>
#include <cuda_fp16.h>

#define HID   128
#define NMAX  50000
#define EMAX  600000
#define BMAX  512
#define METAD 27

typedef unsigned int       u32;
typedef unsigned long long u64;

// ---------------- scratch (device globals; no allocation allowed) -------------
__device__ float   g_dinv[NMAX];
__device__ __half2 g_hsh[(size_t)NMAX * 64];   // hs messages, fp16
__device__ __half  g_hh [(size_t)NMAX * HID];  // h activations, fp16
__device__ float   g_sum[BMAX * HID];
__device__ float   g_cnt[BMAX];
__device__ int     g_indeg[NMAX];
__device__ int     g_off  [NMAX];
__device__ int     g_cur  [NMAX];
__device__ int     g_bsum [256];
__device__ int     g_srcs [EMAX];
__device__ int     g_ei64;
__device__ int     g_ba64;

__device__ __forceinline__ int fetch_idx(const int* __restrict__ p, size_t i, int is64) {
    return is64 ? p[2 * i] : p[i];
}

__device__ __forceinline__ u32 smem_addr(const void* p) {
    u32 a;
    asm("{ .reg .u64 t; cvta.to.shared.u64 t, %1; cvt.u32.u64 %0, t; }" : "=r"(a) : "l"(p));
    return a;
}
__device__ __forceinline__ void ldsm4(u32* r, u32 addr) {
    asm volatile("ldmatrix.sync.aligned.m8n8.x4.shared.b16 {%0,%1,%2,%3}, [%4];"
        : "=r"(r[0]), "=r"(r[1]), "=r"(r[2]), "=r"(r[3]) : "r"(addr));
}
__device__ __forceinline__ void ldsm4t(u32* r, u32 addr) {
    asm volatile("ldmatrix.sync.aligned.m8n8.x4.trans.shared.b16 {%0,%1,%2,%3}, [%4];"
        : "=r"(r[0]), "=r"(r[1]), "=r"(r[2]), "=r"(r[3]) : "r"(addr));
}
__device__ __forceinline__ void mma16816(float* d, const u32* a, u32 b0, u32 b1) {
    asm volatile("mma.sync.aligned.m16n8k16.row.col.f32.f16.f16.f32 "
        "{%0,%1,%2,%3}, {%4,%5,%6,%7}, {%8,%9}, {%0,%1,%2,%3};"
        : "+f"(d[0]), "+f"(d[1]), "+f"(d[2]), "+f"(d[3])
        : "r"(a[0]), "r"(a[1]), "r"(a[2]), "r"(a[3]), "r"(b0), "r"(b1));
}

// ---------------- init (+ dtype detect on thread 0 of block 0) ----------------
__global__ void init_kernel(const int* __restrict__ ei, const int* __restrict__ batch,
                            int E, int N, int B) {
    int i = blockIdx.x * blockDim.x + threadIdx.x;
    if (i == 0) {
        int all_zero = 1;
        for (int k = 0; k < 48; k++) {
            size_t j = (size_t)(((long long)(k + 1) * (E - 2)) / 49);
            if (ei[2 * j + 1] != 0) { all_zero = 0; break; }
        }
        g_ei64 = all_zero;
        all_zero = 1;
        for (int k = 0; k < 48; k++) {
            size_t j = (size_t)(N / 2 + ((long long)k * (N / 2 - 2)) / 48);
            if (batch[2 * (j / 2) + 1] != 0) { all_zero = 0; break; }
        }
        g_ba64 = all_zero;
    }
    if (i < N) { g_indeg[i] = 0; g_cur[i] = 0; }
    if (i < B * HID) g_sum[i] = 0.0f;
    if (i < B) g_cnt[i] = 0.0f;
}

// ---------------- in-degree histogram ------------------------------------------
__global__ void hist_kernel(const int* __restrict__ ei, int E) {
    int e = blockIdx.x * blockDim.x + threadIdx.x;
    if (e < E) atomicAdd(&g_indeg[fetch_idx(ei, (size_t)E + e, g_ei64)], 1);
}

// ---------------- scan phase 1: per-block exclusive scan (+ dinv fused) --------
__global__ void scan_block_kernel(int N) {
    __shared__ int sh[256];
    int i = blockIdx.x * 256 + threadIdx.x;
    int v = (i < N) ? g_indeg[i] : 0;
    if (i < N) g_dinv[i] = rsqrtf((float)(v + 1));   // deg incl self loop
    sh[threadIdx.x] = v;
    __syncthreads();
#pragma unroll
    for (int s = 1; s < 256; s <<= 1) {
        int t = (threadIdx.x >= s) ? sh[threadIdx.x - s] : 0;
        __syncthreads();
        sh[threadIdx.x] += t;
        __syncthreads();
    }
    if (i < N) g_off[i] = sh[threadIdx.x] - v;
    if (threadIdx.x == 255) g_bsum[blockIdx.x] = sh[255];
}

// ---------------- scan phase 2: add block prefix --------------------------------
__global__ void scan_add_kernel(int N) {
    __shared__ int base_sh;
    if (threadIdx.x < 32) {
        int run = 0;
        for (int b = threadIdx.x; b < blockIdx.x; b += 32) run += g_bsum[b];
#pragma unroll
        for (int s = 16; s > 0; s >>= 1) run += __shfl_down_sync(0xffffffffu, run, s);
        if (threadIdx.x == 0) base_sh = run;
    }
    __syncthreads();
    int i = blockIdx.x * 256 + threadIdx.x;
    if (i < N) g_off[i] += base_sh;
}

// ---------------- fill: srcs sorted by dst --------------------------------------
__global__ void fill_kernel(const int* __restrict__ ei, int E) {
    int e = blockIdx.x * blockDim.x + threadIdx.x;
    if (e >= E) return;
    int is64 = g_ei64;
    int s = fetch_idx(ei, (size_t)e, is64);
    int d = fetch_idx(ei, (size_t)E + e, is64);
    int pos = g_off[d] + atomicAdd(&g_cur[d], 1);
    g_srcs[pos] = s;
}

// ---------------- GEMM (mma.sync HMMA): hs(fp16) = dinv[row] * (A @ W) ---------
// 128x128 block tile, 512 threads = 16 warps (4x4), warp tile 32x32, fp32 acc.
// 2 blocks/SM -> 32 resident warps to hide the fill's long-scoreboard stalls.
#define PITCH 136
__global__ __launch_bounds__(512, 2)
void gemm_kernel(const float* __restrict__ Aext, const float* __restrict__ W,
                 int M, int use_gh)
{
    extern __shared__ __align__(16) __half smem[];
    __half* As = smem;                 // [128][PITCH]
    __half* Bs = smem + 128 * PITCH;   // [128][PITCH]

    int tid = threadIdx.x;
    int row0 = blockIdx.x * 128;
    bool full = (row0 + 128 <= M);

    // ---- fill A ----
    if (use_gh) {
#pragma unroll
        for (int i = 0; i < 4; i++) {
            int idx = i * 512 + tid;        // 2048 uint4 slots: 128 rows x 16
            int m   = idx >> 4;
            int k8  = idx & 15;
            uint4 v;
            if (full || (row0 + m) < M)
                v = *(const uint4*)(g_hh + (size_t)(row0 + m) * HID + k8 * 8);
            else
                v = make_uint4(0, 0, 0, 0);
            *(uint4*)(As + m * PITCH + k8 * 8) = v;
        }
    } else {
#pragma unroll
        for (int i = 0; i < 8; i++) {
            int idx = i * 512 + tid;        // 4096 float4 slots: 128 rows x 32
            int m   = idx >> 5;
            int k4  = idx & 31;
            float4 v;
            if (full || (row0 + m) < M)
                v = *(const float4*)(Aext + (size_t)(row0 + m) * HID + k4 * 4);
            else
                v = make_float4(0.f, 0.f, 0.f, 0.f);
            __half2 h0 = __floats2half2_rn(v.x, v.y);
            __half2 h1 = __floats2half2_rn(v.z, v.w);
            uint2 st; st.x = *(u32*)&h0; st.y = *(u32*)&h1;
            *(uint2*)(As + m * PITCH + k4 * 4) = st;
        }
    }
    // ---- fill B: W [k][n] fp32 -> fp16 ----
#pragma unroll
    for (int i = 0; i < 8; i++) {
        int idx = i * 512 + tid;
        int k   = idx >> 5;
        int n4  = idx & 31;
        float4 v = *(const float4*)(W + (size_t)k * 128 + n4 * 4);
        __half2 h0 = __floats2half2_rn(v.x, v.y);
        __half2 h1 = __floats2half2_rn(v.z, v.w);
        uint2 st; st.x = *(u32*)&h0; st.y = *(u32*)&h1;
        *(uint2*)(Bs + k * PITCH + n4 * 4) = st;
    }
    __syncthreads();

    int wid  = tid >> 5;
    int lane = tid & 31;
    int wm = (wid & 3) * 32;     // warp m offset (4 warps over M)
    int wn = (wid >> 2) * 32;    // warp n offset (4 warps over N)

    float acc[2][4][4];
#pragma unroll
    for (int mt = 0; mt < 2; mt++)
#pragma unroll
        for (int nt = 0; nt < 4; nt++)
#pragma unroll
            for (int j = 0; j < 4; j++) acc[mt][nt][j] = 0.f;

    int a_row_in = lane & 15;
    int a_koff   = (lane >> 4) * 8;
    int b_row_in = (lane & 7) + ((lane >> 3) & 1) * 8;
    int b_noff   = (lane >> 4) * 8;

#pragma unroll
    for (int ks = 0; ks < 8; ks++) {
        int k = ks * 16;
        u32 af[2][4], bf[2][4];
#pragma unroll
        for (int mt = 0; mt < 2; mt++) {
            const __half* p = As + (wm + mt * 16 + a_row_in) * PITCH + k + a_koff;
            ldsm4(af[mt], smem_addr(p));
        }
#pragma unroll
        for (int nt2 = 0; nt2 < 2; nt2++) {
            const __half* p = Bs + (k + b_row_in) * PITCH + wn + nt2 * 16 + b_noff;
            ldsm4t(bf[nt2], smem_addr(p));
        }
#pragma unroll
        for (int mt = 0; mt < 2; mt++)
#pragma unroll
            for (int nt = 0; nt < 4; nt++) {
                int g = nt >> 1, h = nt & 1;
                mma16816(acc[mt][nt], af[mt], bf[g][h * 2], bf[g][h * 2 + 1]);
            }
    }

    // ---- epilogue: scale dinv, write fp16 messages ----
    int gr = lane >> 2;
    int tc = lane & 3;
#pragma unroll
    for (int mt = 0; mt < 2; mt++) {
        int ra = row0 + wm + mt * 16 + gr;
        int rb = ra + 8;
        float dva = (ra < M) ? g_dinv[ra] : 0.f;
        float dvb = (rb < M) ? g_dinv[rb] : 0.f;
#pragma unroll
        for (int nt = 0; nt < 4; nt++) {
            int col = wn + nt * 8 + tc * 2;
            if (ra < M)
                g_hsh[(size_t)ra * 64 + (col >> 1)] =
                    __floats2half2_rn(acc[mt][nt][0] * dva, acc[mt][nt][1] * dva);
            if (rb < M)
                g_hsh[(size_t)rb * 64 + (col >> 1)] =
                    __floats2half2_rn(acc[mt][nt][2] * dvb, acc[mt][nt][3] * dvb);
        }
    }
}

// ---------------- gather: fp16 HADD2 accumulation, index-prefetch pipeline -----
__global__ void gather_kernel(const float* __restrict__ bias, int N,
                              const int* __restrict__ batch, int do_pool)
{
    int gid = blockIdx.x * blockDim.x + threadIdx.x;
    int row = gid >> 5;
    if (row >= N) return;
    int lane = gid & 31;

    const uint2* hs2 = (const uint2*)g_hsh;
    const int* __restrict__ srcs = g_srcs;
    int beg = g_off[row];
    int cnt = g_indeg[row];

    uint2 sv = hs2[(size_t)row * 32 + lane];
    __half2 aAlo = *(const __half2*)&sv.x;
    __half2 aAhi = *(const __half2*)&sv.y;
    __half2 aBlo = __floats2half2_rn(0.f, 0.f);
    __half2 aBhi = aBlo;

#define ACCA(rw) do { uint2 _v = hs2[(size_t)(rw) * 32 + lane];             \
        aAlo = __hadd2(aAlo, *(const __half2*)&_v.x);                        \
        aAhi = __hadd2(aAhi, *(const __half2*)&_v.y); } while (0)
#define ACCB(rw) do { uint2 _v = hs2[(size_t)(rw) * 32 + lane];             \
        aBlo = __hadd2(aBlo, *(const __half2*)&_v.x);                        \
        aBhi = __hadd2(aBhi, *(const __half2*)&_v.y); } while (0)

    int k = 0;
    if (cnt >= 4) {
        int s0 = srcs[beg], s1 = srcs[beg + 1], s2 = srcs[beg + 2], s3 = srcs[beg + 3];
        for (; k + 8 <= cnt; k += 4) {
            int t0 = srcs[beg + k + 4], t1 = srcs[beg + k + 5];
            int t2 = srcs[beg + k + 6], t3 = srcs[beg + k + 7];
            ACCA(s0); ACCB(s1); ACCA(s2); ACCB(s3);
            s0 = t0; s1 = t1; s2 = t2; s3 = t3;
        }
        ACCA(s0); ACCB(s1); ACCA(s2); ACCB(s3);
        k += 4;
    }
    for (; k < cnt; k++) ACCA(srcs[beg + k]);
#undef ACCA
#undef ACCB

    float2 fAlo = __half22float2(aAlo), fAhi = __half22float2(aAhi);
    float2 fBlo = __half22float2(aBlo), fBhi = __half22float2(aBhi);
    float4 a;
    a.x = fAlo.x + fBlo.x; a.y = fAlo.y + fBlo.y;
    a.z = fAhi.x + fBhi.x; a.w = fAhi.y + fBhi.y;

    float dv = g_dinv[row];
    float4 bb = ((const float4*)bias)[lane];
    a.x = fmaxf(fmaf(a.x, dv, bb.x), 0.f);
    a.y = fmaxf(fmaf(a.y, dv, bb.y), 0.f);
    a.z = fmaxf(fmaf(a.z, dv, bb.z), 0.f);
    a.w = fmaxf(fmaf(a.w, dv, bb.w), 0.f);

    if (!do_pool) {
        __half2 h0 = __floats2half2_rn(a.x, a.y);
        __half2 h1 = __floats2half2_rn(a.z, a.w);
        uint2 st; st.x = *(u32*)&h0; st.y = *(u32*)&h1;
        *(uint2*)(g_hh + (size_t)row * HID + lane * 4) = st;
    } else {
        int b = fetch_idx(batch, (size_t)row, g_ba64);
        float* p = g_sum + b * 128 + lane * 4;
        atomicAdd(p + 0, a.x);
        atomicAdd(p + 1, a.y);
        atomicAdd(p + 2, a.z);
        atomicAdd(p + 3, a.w);
        if (lane == 0) atomicAdd(&g_cnt[b], 1.0f);
    }
}

// ---------------- MLP head ------------------------------------------------------
__global__ __launch_bounds__(128)
void head_kernel(const float* __restrict__ meta,
                 const float* __restrict__ Wh1, const float* __restrict__ bh1,
                 const float* __restrict__ Wh2, const float* __restrict__ bh2,
                 float* __restrict__ out)
{
    int b = blockIdx.x;
    int j = threadIdx.x;
    __shared__ float zin[HID + METAD];
    __shared__ float red[128];

    float inv = 1.0f / fmaxf(g_cnt[b], 1.0f);
    zin[j] = g_sum[b * HID + j] * inv;
    if (j < METAD) zin[HID + j] = meta[b * METAD + j];
    __syncthreads();

    float acc = bh1[j];
#pragma unroll
    for (int k = 0; k < HID + METAD; k++)
        acc = fmaf(zin[k], Wh1[k * HID + j], acc);
    red[j] = fmaxf(acc, 0.0f) * Wh2[j];
    __syncthreads();
#pragma unroll
    for (int s = 64; s > 0; s >>= 1) {
        if (j < s) red[j] += red[j + s];
        __syncthreads();
    }
    if (j == 0) out[b] = red[0] + bh2[0];
}

// --------------------------------------------------------------------------------
extern "C" void kernel_launch(void* const* d_in, const int* in_sizes, int n_in,
                              void* d_out, int out_size)
{
    const float* x     = (const float*)d_in[0];
    const int*   ei    = (const int*)d_in[1];
    const int*   batch = (const int*)d_in[2];
    const float* meta  = (const float*)d_in[3];
    const float* W1 = (const float*)d_in[4];  const float* b1 = (const float*)d_in[5];
    const float* W2 = (const float*)d_in[6];  const float* b2 = (const float*)d_in[7];
    const float* W3 = (const float*)d_in[8];  const float* b3 = (const float*)d_in[9];
    const float* Wh1 = (const float*)d_in[10]; const float* bh1 = (const float*)d_in[11];
    const float* Wh2 = (const float*)d_in[12]; const float* bh2 = (const float*)d_in[13];
    float* out = (float*)d_out;

    int N = in_sizes[0] / HID;
    int E = in_sizes[1] / 2;
    int B = in_sizes[3] / METAD;

    const int DSM = 2 * 128 * PITCH * (int)sizeof(__half);   // 69632
    cudaFuncSetAttribute(gemm_kernel, cudaFuncAttributeMaxDynamicSharedMemorySize, DSM);

    int initN = (N > B * HID) ? N : B * HID;
    int gblocks = (N + 127) / 128;
    int wblocks = (int)(((long long)N * 32 + 255) / 256);
    int nscan   = (N + 255) / 256;

    // gemm1 at launch slot 4 (the slot ncu samples); dinv fused into scan_block
    init_kernel      <<<(initN + 255) / 256, 256>>>(ei, batch, E, N, B);
    hist_kernel      <<<(E + 255) / 256, 256>>>(ei, E);
    scan_block_kernel<<<nscan, 256>>>(N);
    gemm_kernel      <<<gblocks, 512, DSM>>>(x, W1, N, 0);
    scan_add_kernel  <<<nscan, 256>>>(N);
    fill_kernel      <<<(E + 255) / 256, 256>>>(ei, E);

    gather_kernel<<<wblocks, 256>>>(b1, N, batch, 0);
    gemm_kernel  <<<gblocks, 512, DSM>>>(nullptr, W2, N, 1);
    gather_kernel<<<wblocks, 256>>>(b2, N, batch, 0);
    gemm_kernel  <<<gblocks, 512, DSM>>>(nullptr, W3, N, 1);
    gather_kernel<<<wblocks, 256>>>(b3, N, batch, 1);

    head_kernel<<<B, 128>>>(meta, Wh1, bh1, Wh2, bh2, out);
}